// round 16
// baseline (speedup 1.0000x reference)
#include <cuda_runtime.h>
#include <cuda_fp16.h>
#include <math.h>
#include <stdint.h>

#define NN 4
#define LL 4096
#define HH 16
#define DD 64
#define MM 64
#define CC 128
#define GG 32
#define EPSF 1e-6f

typedef unsigned int u32;

// Scratch: per-chunk kvT stored as packed fp16 pairs (half2 along d) + fp32 ksum.
static __device__ u32   g_kvh[(size_t)NN * GG * HH * MM * (DD / 2)];   // 16.7MB
static __device__ float g_ksum[(size_t)NN * GG * HH * DD];

__device__ __forceinline__ float phi(float x) { return x > 0.f ? x + 1.f : __expf(x); }

__device__ __forceinline__ u32 rnd2h(float x0, float x1) {
    __half2 hh = __floats2half2_rn(x0, x1);
    return *reinterpret_cast<u32*>(&hh);
}
__device__ __forceinline__ float2 h2f(u32 u) {
    return __half22float2(*reinterpret_cast<__half2*>(&u));
}

__device__ __forceinline__ u32 smem_u32(const void* p) {
    u32 a;
    asm("{ .reg .u64 t; cvta.to.shared.u64 t, %1; cvt.u32.u64 %0, t; }" : "=r"(a) : "l"(p));
    return a;
}
__device__ __forceinline__ void ldm4(u32& r0, u32& r1, u32& r2, u32& r3, u32 a) {
    asm volatile("ldmatrix.sync.aligned.m8n8.x4.shared.b16 {%0,%1,%2,%3},[%4];"
                 : "=r"(r0), "=r"(r1), "=r"(r2), "=r"(r3) : "r"(a));
}
__device__ __forceinline__ void ldm4t(u32& r0, u32& r1, u32& r2, u32& r3, u32 a) {
    asm volatile("ldmatrix.sync.aligned.m8n8.x4.trans.shared.b16 {%0,%1,%2,%3},[%4];"
                 : "=r"(r0), "=r"(r1), "=r"(r2), "=r"(r3) : "r"(a));
}
__device__ __forceinline__ void mma16816(float* d, u32 a0, u32 a1, u32 a2, u32 a3,
                                         u32 b0, u32 b1) {
    asm("mma.sync.aligned.m16n8k16.row.col.f32.f16.f16.f32 "
        "{%0,%1,%2,%3},{%4,%5,%6,%7},{%8,%9},{%0,%1,%2,%3};"
        : "+f"(d[0]), "+f"(d[1]), "+f"(d[2]), "+f"(d[3])
        : "r"(a0), "r"(a1), "r"(a2), "r"(a3), "r"(b0), "r"(b1));
}
__device__ __forceinline__ u32 off128(int row, int kb) {
    return (u32)(row * 128) + (u32)(((((kb >> 4) & 7) ^ (row & 7)) << 4) | (kb & 15));
}

// ---------------------------------------------------------------------------
// Kernel A: kvT[m][d] = sum_c v[c][m] * phi(k)[c][d]
// ---------------------------------------------------------------------------
__global__ void __launch_bounds__(256, 3) chunk_state_kernel(
    const float* __restrict__ k, const float* __restrict__ v)
{
    extern __shared__ char sm_[];
    const int KN = 0, VN = 16384, KSP = 32768;
    u32 sb = smem_u32(sm_);

    int tid = threadIdx.x, lane = tid & 31, wid = tid >> 5;
    int bid = blockIdx.x;
    int h = bid % HH;
    int gc = (bid / HH) % GG;
    int n = bid / (HH * GG);
    size_t base = (((size_t)n * LL + (size_t)gc * CC) * HH + h) * DD;

#pragma unroll
    for (int hb = 0; hb < 2; hb++) {
        float4 kr[4], vr[4];
#pragma unroll
        for (int t = 0; t < 4; t++) {
            int i = tid + (hb * 4 + t) * 256;
            int c = i >> 4, dq = (i & 15) << 2;
            size_t off = base + (size_t)c * (HH * DD) + dq;
            kr[t] = *(const float4*)(k + off);
            vr[t] = *(const float4*)(v + off);
        }
#pragma unroll
        for (int t = 0; t < 4; t++) {
            int i = tid + (hb * 4 + t) * 256;
            int c = i >> 4, dq = (i & 15) << 2;
            u32 ob = off128(c, dq * 2);
            *(uint2*)(sm_ + KN + ob) =
                make_uint2(rnd2h(phi(kr[t].x), phi(kr[t].y)),
                           rnd2h(phi(kr[t].z), phi(kr[t].w)));
            *(uint2*)(sm_ + VN + ob) =
                make_uint2(rnd2h(vr[t].x, vr[t].y), rnd2h(vr[t].z, vr[t].w));
        }
    }
    __syncthreads();

    int grp = lane >> 2, tg = lane & 3;
    int m0 = (wid >> 1) * 16, n0 = (wid & 1) * 32;
    int rAt = (lane & 7) + ((lane >> 4) & 1) * 8;
    int cAb = m0 * 2 + ((lane >> 3) & 1) * 16;
    int rBt = (lane & 7) + ((lane >> 3) & 1) * 8;
    int cBb = (lane >> 4) * 16;

    float acc[4][4] = {};
#pragma unroll
    for (int ks = 0; ks < 8; ks++) {
        u32 a0, a1, a2, a3;
        ldm4t(a0, a1, a2, a3, sb + VN + off128(ks * 16 + rAt, cAb));
#pragma unroll
        for (int jb = 0; jb < 2; jb++) {
            u32 b0, b1, b2, b3;
            ldm4t(b0, b1, b2, b3,
                  sb + KN + off128(ks * 16 + rBt, (n0 + jb * 16) * 2 + cBb));
            mma16816(acc[2 * jb],     a0, a1, a2, a3, b0, b1);
            mma16816(acc[2 * jb + 1], a0, a1, a2, a3, b2, b3);
        }
    }

    u32* kvout = g_kvh + (size_t)bid * (MM * DD / 2);
#pragma unroll
    for (int j = 0; j < 4; j++) {
        int dc = n0 + (j >> 1) * 16 + (j & 1) * 8 + tg * 2;
        kvout[(size_t)(m0 + grp) * 32 + (dc >> 1)]     = rnd2h(acc[j][0], acc[j][1]);
        kvout[(size_t)(m0 + grp + 8) * 32 + (dc >> 1)] = rnd2h(acc[j][2], acc[j][3]);
    }

    {
        float* ksp = (float*)(sm_ + KSP);
        int d = tid & 63, qd = tid >> 6;
        float s = 0.f;
#pragma unroll 8
        for (int cc = 0; cc < 32; cc++)
            s += __half2float(*(const __half*)(sm_ + KN + off128(qd * 32 + cc, d * 2)));
        ksp[qd * 64 + d] = s;
    }
    __syncthreads();
    if (tid < 64) {
        const float* ksp = (const float*)(sm_ + KSP);
        g_ksum[(size_t)bid * DD + tid] =
            ksp[tid] + ksp[64 + tid] + ksp[128 + tid] + ksp[192 + tid];
    }
}

// ---------------------------------------------------------------------------
// Kernel B: exclusive prefix over chunks. Latency-optimized: 4 threads per
// element chain, each preloads its 8 chunks (MLP 8), shfl-scan over subs.
// grid = NN*HH*16 = 1024 blocks, 256 threads.
// ---------------------------------------------------------------------------
__global__ void __launch_bounds__(256) prefix_kernel()
{
    int blk = blockIdx.x;
    int nh = blk >> 4, seg = blk & 15;
    int n = nh / HH, h = nh % HH;
    int tid = threadIdx.x;
    int sub = tid & 3;
    int elem = seg * 64 + (tid >> 2);                  // uint2 index 0..1023
    const size_t gstr = (size_t)HH * (MM * DD / 2);    // u32 per chunk step
    u32* basep = g_kvh + (((size_t)(n * GG) * HH) + h) * (MM * DD / 2) + elem * 2;

    uint2 vals[8];
#pragma unroll
    for (int t = 0; t < 8; t++)
        vals[t] = *(uint2*)(basep + (size_t)(sub * 8 + t) * gstr);

    float4 tot = make_float4(0.f, 0.f, 0.f, 0.f);
#pragma unroll
    for (int t = 0; t < 8; t++) {
        float2 f0 = h2f(vals[t].x), f1 = h2f(vals[t].y);
        tot.x += f0.x; tot.y += f0.y; tot.z += f1.x; tot.w += f1.y;
    }
    // inclusive scan over the 4 subs, then make exclusive offset
    float4 incl = tot;
#pragma unroll
    for (int d = 1; d < 4; d <<= 1) {
        float4 t;
        t.x = __shfl_up_sync(0xffffffffu, incl.x, d, 4);
        t.y = __shfl_up_sync(0xffffffffu, incl.y, d, 4);
        t.z = __shfl_up_sync(0xffffffffu, incl.z, d, 4);
        t.w = __shfl_up_sync(0xffffffffu, incl.w, d, 4);
        if (sub >= d) { incl.x += t.x; incl.y += t.y; incl.z += t.z; incl.w += t.w; }
    }
    float4 run = make_float4(incl.x - tot.x, incl.y - tot.y,
                             incl.z - tot.z, incl.w - tot.w);
#pragma unroll
    for (int t = 0; t < 8; t++) {
        uint2 o = make_uint2(rnd2h(run.x, run.y), rnd2h(run.z, run.w));
        float2 f0 = h2f(vals[t].x), f1 = h2f(vals[t].y);
        *(uint2*)(basep + (size_t)(sub * 8 + t) * gstr) = o;
        run.x += f0.x; run.y += f0.y; run.z += f1.x; run.w += f1.y;
    }

    // ksum prefix: seg-0 blocks, threads 0..63 (16 float4 chains x 4 subs)
    if (seg == 0 && tid < 64) {
        int fe = tid >> 2;                              // float4 index 0..15
        const size_t kstr = (size_t)HH * DD;            // floats per chunk step
        float* kb = g_ksum + (((size_t)(n * GG) * HH) + h) * DD + fe * 4;
        float4 kv[8];
#pragma unroll
        for (int t = 0; t < 8; t++)
            kv[t] = *(float4*)(kb + (size_t)(sub * 8 + t) * kstr);
        float4 kt = make_float4(0.f, 0.f, 0.f, 0.f);
#pragma unroll
        for (int t = 0; t < 8; t++) {
            kt.x += kv[t].x; kt.y += kv[t].y; kt.z += kv[t].z; kt.w += kv[t].w;
        }
        float4 ki = kt;
#pragma unroll
        for (int d = 1; d < 4; d <<= 1) {
            float4 t;
            t.x = __shfl_up_sync(0xffffffffu, ki.x, d, 4);
            t.y = __shfl_up_sync(0xffffffffu, ki.y, d, 4);
            t.z = __shfl_up_sync(0xffffffffu, ki.z, d, 4);
            t.w = __shfl_up_sync(0xffffffffu, ki.w, d, 4);
            if (sub >= d) { ki.x += t.x; ki.y += t.y; ki.z += t.z; ki.w += t.w; }
        }
        float4 kr = make_float4(ki.x - kt.x, ki.y - kt.y, ki.z - kt.z, ki.w - kt.w);
#pragma unroll
        for (int t = 0; t < 8; t++) {
            float4 cur = kv[t];
            *(float4*)(kb + (size_t)(sub * 8 + t) * kstr) = kr;
            kr.x += cur.x; kr.y += cur.y; kr.z += cur.z; kr.w += cur.w;
        }
    }
}

// ---------------------------------------------------------------------------
// Kernel C: pure fp16 MMA; z fully in fp32 (intra rowsum + q.ksum from
// unpacked Q fragments) -> no z-MMA, WH trimmed to 64 rows -> 4 CTAs/SM.
// planes: QH 0, KH 16K, VN 32K, WH 48K (64x128B). total 56KB.
// ---------------------------------------------------------------------------
#define QHo 0
#define KHo 16384
#define VNo 32768
#define WHo 49152
#define SMEM_C 57344

__global__ void __launch_bounds__(256, 4) output_kernel(
    const float* __restrict__ q, const float* __restrict__ k,
    const float* __restrict__ v, float* __restrict__ out)
{
    extern __shared__ char sm_[];
    u32 sb = smem_u32(sm_);

    int tid = threadIdx.x, lane = tid & 31, wid = tid >> 5;
    int bid = blockIdx.x;
    int h = bid % HH;
    int gc = (bid / HH) % GG;
    int n = bid / (HH * GG);
    size_t base = (((size_t)n * LL + (size_t)gc * CC) * HH + h) * DD;

    // ---- KV' rows 0..63 via cp.async (512 x 16B) ----
    {
        const u32* kvp = g_kvh + (size_t)bid * (MM * DD / 2);
#pragma unroll
        for (int t = 0; t < 2; t++) {
            int i = tid + t * 256;
            int m = i >> 3, du = (i & 7) * 4;
            u32 dst = sb + WHo + off128(m, du * 4);
            const void* src = kvp + (size_t)m * 32 + du;
            asm volatile("cp.async.ca.shared.global [%0], [%1], 16;"
                         :: "r"(dst), "l"(src));
        }
        asm volatile("cp.async.commit_group;");
    }

    // ---- merged, batched q/k/v loader (all rounded to fp16) ----
#pragma unroll
    for (int bb = 0; bb < 4; bb++) {
        float4 qr[2], kr[2], vr[2];
#pragma unroll
        for (int t = 0; t < 2; t++) {
            int i = tid + (bb * 2 + t) * 256;
            int c = i >> 4, dq = (i & 15) << 2;
            size_t off = base + (size_t)c * (HH * DD) + dq;
            qr[t] = *(const float4*)(q + off);
            kr[t] = *(const float4*)(k + off);
            vr[t] = *(const float4*)(v + off);
        }
#pragma unroll
        for (int t = 0; t < 2; t++) {
            int i = tid + (bb * 2 + t) * 256;
            int c = i >> 4, dq = (i & 15) << 2;
            u32 ob = off128(c, dq * 2);
            *(uint2*)(sm_ + QHo + ob) =
                make_uint2(rnd2h(phi(qr[t].x), phi(qr[t].y)),
                           rnd2h(phi(qr[t].z), phi(qr[t].w)));
            *(uint2*)(sm_ + KHo + ob) =
                make_uint2(rnd2h(phi(kr[t].x), phi(kr[t].y)),
                           rnd2h(phi(kr[t].z), phi(kr[t].w)));
            *(uint2*)(sm_ + VNo + ob) =
                make_uint2(rnd2h(vr[t].x, vr[t].y), rnd2h(vr[t].z, vr[t].w));
        }
    }
    asm volatile("cp.async.wait_group 0;" ::: "memory");
    __syncthreads();

    const int perm[8] = { 0, 1, 2, 3, 7, 6, 5, 4 };
    int wb = perm[wid];
    int m0 = wb * 16;
    int grp = lane >> 2, tg = lane & 3;
    int rA = m0 + ((lane >> 3) & 1) * 8 + (lane & 7);
    int rB = (lane >> 4) * 8 + (lane & 7);
    int kbA0 = 16 * (lane >> 4);
    int kbB0 = 16 * ((lane >> 3) & 1);
    int rBt = (lane & 7) + ((lane >> 3) & 1) * 8;   // natural-V trans B
    int cBb = (lane >> 4) * 16;
    int r0 = m0 + grp, r1 = r0 + 8;

    // ---- cache Q fragments ----
    u32 qh[4][4];
#pragma unroll
    for (int ks = 0; ks < 4; ks++)
        ldm4(qh[ks][0], qh[ks][1], qh[ks][2], qh[ks][3], sb + QHo + off128(rA, 32 * ks + kbA0));

    // ---- inter z = q . ksum_prev (fp32, from unpacked Q fragments) ----
    float zs0 = 0.f, zs1 = 0.f;
    {
        const float2* ksp = (const float2*)(g_ksum + (size_t)bid * DD);
#pragma unroll
        for (int ks = 0; ks < 4; ks++) {
            float2 k0 = ksp[8 * ks + tg];
            float2 k1 = ksp[8 * ks + 4 + tg];
            float2 q0 = h2f(qh[ks][0]), q2 = h2f(qh[ks][2]);
            float2 q1 = h2f(qh[ks][1]), q3 = h2f(qh[ks][3]);
            zs0 += q0.x * k0.x + q0.y * k0.y + q2.x * k1.x + q2.y * k1.y;
            zs1 += q1.x * k0.x + q1.y * k0.y + q3.x * k1.x + q3.y * k1.y;
        }
    }

    float accO[8][4] = {};

    // ---- inter: O += Q KV'^T (N=64) ----
#pragma unroll
    for (int ks = 0; ks < 4; ks++) {
        int kb = 32 * ks + kbB0;
#pragma unroll
        for (int jb = 0; jb < 4; jb++) {
            u32 b0, b1, b2, b3;
            ldm4(b0, b1, b2, b3, sb + WHo + off128(jb * 16 + rB, kb));
            mma16816(accO[2 * jb],     qh[ks][0], qh[ks][1], qh[ks][2], qh[ks][3], b0, b1);
            mma16816(accO[2 * jb + 1], qh[ks][0], qh[ks][1], qh[ks][2], qh[ks][3], b2, b3);
        }
    }

    // ---- S blocks (jb <= wb): GEMM1 -> mask (+fp32 z) -> round -> intra ----
#pragma unroll
    for (int jb = 0; jb < 8; jb++) {
        if (jb <= wb) {
            float s0[4] = {}, s1[4] = {};
#pragma unroll
            for (int ks = 0; ks < 4; ks++) {
                u32 b0, b1, b2, b3;
                ldm4(b0, b1, b2, b3, sb + KHo + off128(jb * 16 + rB, 32 * ks + kbB0));
                mma16816(s0, qh[ks][0], qh[ks][1], qh[ks][2], qh[ks][3], b0, b1);
                mma16816(s1, qh[ks][0], qh[ks][1], qh[ks][2], qh[ks][3], b2, b3);
            }
            int cA = jb * 16 + tg * 2, cB = cA + 8;
            if (cA > r0)     s0[0] = 0.f;
            if (cA + 1 > r0) s0[1] = 0.f;
            if (cA > r1)     s0[2] = 0.f;
            if (cA + 1 > r1) s0[3] = 0.f;
            if (cB > r0)     s1[0] = 0.f;
            if (cB + 1 > r0) s1[1] = 0.f;
            if (cB > r1)     s1[2] = 0.f;
            if (cB + 1 > r1) s1[3] = 0.f;
            zs0 += (s0[0] + s0[1]) + (s1[0] + s1[1]);
            zs1 += (s0[2] + s0[3]) + (s1[2] + s1[3]);
            u32 sh0 = rnd2h(s0[0], s0[1]);
            u32 sh1 = rnd2h(s0[2], s0[3]);
            u32 sh2 = rnd2h(s1[0], s1[1]);
            u32 sh3 = rnd2h(s1[2], s1[3]);
#pragma unroll
            for (int vjb = 0; vjb < 4; vjb++) {
                u32 b0, b1, b2, b3;
                ldm4t(b0, b1, b2, b3,
                      sb + VNo + off128(jb * 16 + rBt, vjb * 32 + cBb));
                mma16816(accO[2 * vjb],     sh0, sh1, sh2, sh3, b0, b1);
                mma16816(accO[2 * vjb + 1], sh0, sh1, sh2, sh3, b2, b3);
            }
        }
    }
    zs0 += __shfl_xor_sync(0xffffffffu, zs0, 1);
    zs0 += __shfl_xor_sync(0xffffffffu, zs0, 2);
    zs1 += __shfl_xor_sync(0xffffffffu, zs1, 1);
    zs1 += __shfl_xor_sync(0xffffffffu, zs1, 2);

    // ---- normalize + store ----
    float rz0 = 1.0f / (zs0 + EPSF);
    float rz1 = 1.0f / (zs1 + EPSF);
    float* op0 = out + (((size_t)n * LL + (size_t)gc * CC + r0) * HH + h) * MM;
    float* op1 = op0 + (size_t)8 * HH * MM;
#pragma unroll
    for (int j = 0; j < 8; j++) {
        int c0 = j * 8 + tg * 2;
        *(float2*)(op0 + c0) = make_float2(accO[j][0] * rz0, accO[j][1] * rz0);
        *(float2*)(op1 + c0) = make_float2(accO[j][2] * rz1, accO[j][3] * rz1);
    }
}

// ---------------------------------------------------------------------------
extern "C" void kernel_launch(void* const* d_in, const int* in_sizes, int n_in,
                              void* d_out, int out_size)
{
    const float* q = (const float*)d_in[0];
    const float* k = (const float*)d_in[1];
    const float* v = (const float*)d_in[2];
    float* out = (float*)d_out;

    const int SMEM_A = 33792;

    cudaFuncSetAttribute(chunk_state_kernel,
                         cudaFuncAttributeMaxDynamicSharedMemorySize, SMEM_A);
    cudaFuncSetAttribute(output_kernel,
                         cudaFuncAttributeMaxDynamicSharedMemorySize, SMEM_C);

    chunk_state_kernel<<<NN * GG * HH, 256, SMEM_A>>>(k, v);
    prefix_kernel<<<NN * HH * 16, 256>>>();
    output_kernel<<<NN * GG * HH, 256, SMEM_C>>>(q, k, v, out);
}

// round 17
// speedup vs baseline: 1.1393x; 1.1393x over previous
#include <cuda_runtime.h>
#include <cuda_fp16.h>
#include <math.h>
#include <stdint.h>

#define NN 4
#define LL 4096
#define HH 16
#define DD 64
#define MM 64
#define CC 128
#define GG 32
#define EPSF 1e-6f

typedef unsigned int u32;

// Scratch: per-chunk kvT stored as packed fp16 pairs (half2 along d) + fp32 ksum.
static __device__ u32   g_kvh[(size_t)NN * GG * HH * MM * (DD / 2)];   // 16.7MB
static __device__ float g_ksum[(size_t)NN * GG * HH * DD];

__device__ __forceinline__ float phi(float x) { return x > 0.f ? x + 1.f : __expf(x); }

__device__ __forceinline__ u32 rnd2h(float x0, float x1) {
    __half2 hh = __floats2half2_rn(x0, x1);
    return *reinterpret_cast<u32*>(&hh);
}
__device__ __forceinline__ float2 h2f(u32 u) {
    return __half22float2(*reinterpret_cast<__half2*>(&u));
}

__device__ __forceinline__ u32 smem_u32(const void* p) {
    u32 a;
    asm("{ .reg .u64 t; cvta.to.shared.u64 t, %1; cvt.u32.u64 %0, t; }" : "=r"(a) : "l"(p));
    return a;
}
__device__ __forceinline__ void ldm4(u32& r0, u32& r1, u32& r2, u32& r3, u32 a) {
    asm volatile("ldmatrix.sync.aligned.m8n8.x4.shared.b16 {%0,%1,%2,%3},[%4];"
                 : "=r"(r0), "=r"(r1), "=r"(r2), "=r"(r3) : "r"(a));
}
__device__ __forceinline__ void ldm4t(u32& r0, u32& r1, u32& r2, u32& r3, u32 a) {
    asm volatile("ldmatrix.sync.aligned.m8n8.x4.trans.shared.b16 {%0,%1,%2,%3},[%4];"
                 : "=r"(r0), "=r"(r1), "=r"(r2), "=r"(r3) : "r"(a));
}
__device__ __forceinline__ void ldm2(u32& r0, u32& r1, u32 a) {
    asm volatile("ldmatrix.sync.aligned.m8n8.x2.shared.b16 {%0,%1},[%2];"
                 : "=r"(r0), "=r"(r1) : "r"(a));
}
__device__ __forceinline__ void mma16816(float* d, u32 a0, u32 a1, u32 a2, u32 a3,
                                         u32 b0, u32 b1) {
    asm("mma.sync.aligned.m16n8k16.row.col.f32.f16.f16.f32 "
        "{%0,%1,%2,%3},{%4,%5,%6,%7},{%8,%9},{%0,%1,%2,%3};"
        : "+f"(d[0]), "+f"(d[1]), "+f"(d[2]), "+f"(d[3])
        : "r"(a0), "r"(a1), "r"(a2), "r"(a3), "r"(b0), "r"(b1));
}
__device__ __forceinline__ u32 off128(int row, int kb) {
    return (u32)(row * 128) + (u32)(((((kb >> 4) & 7) ^ (row & 7)) << 4) | (kb & 15));
}

// ---------------------------------------------------------------------------
// Kernel A: kvT[m][d] = sum_c v[c][m] * phi(k)[c][d]
// ---------------------------------------------------------------------------
__global__ void __launch_bounds__(256, 3) chunk_state_kernel(
    const float* __restrict__ k, const float* __restrict__ v)
{
    extern __shared__ char sm_[];
    const int KN = 0, VN = 16384, KSP = 32768;
    u32 sb = smem_u32(sm_);

    int tid = threadIdx.x, lane = tid & 31, wid = tid >> 5;
    int bid = blockIdx.x;
    int h = bid % HH;
    int gc = (bid / HH) % GG;
    int n = bid / (HH * GG);
    size_t base = (((size_t)n * LL + (size_t)gc * CC) * HH + h) * DD;

#pragma unroll
    for (int hb = 0; hb < 2; hb++) {
        float4 kr[4], vr[4];
#pragma unroll
        for (int t = 0; t < 4; t++) {
            int i = tid + (hb * 4 + t) * 256;
            int c = i >> 4, dq = (i & 15) << 2;
            size_t off = base + (size_t)c * (HH * DD) + dq;
            kr[t] = *(const float4*)(k + off);
            vr[t] = *(const float4*)(v + off);
        }
#pragma unroll
        for (int t = 0; t < 4; t++) {
            int i = tid + (hb * 4 + t) * 256;
            int c = i >> 4, dq = (i & 15) << 2;
            u32 ob = off128(c, dq * 2);
            *(uint2*)(sm_ + KN + ob) =
                make_uint2(rnd2h(phi(kr[t].x), phi(kr[t].y)),
                           rnd2h(phi(kr[t].z), phi(kr[t].w)));
            *(uint2*)(sm_ + VN + ob) =
                make_uint2(rnd2h(vr[t].x, vr[t].y), rnd2h(vr[t].z, vr[t].w));
        }
    }
    __syncthreads();

    int grp = lane >> 2, tg = lane & 3;
    int m0 = (wid >> 1) * 16, n0 = (wid & 1) * 32;
    int rAt = (lane & 7) + ((lane >> 4) & 1) * 8;
    int cAb = m0 * 2 + ((lane >> 3) & 1) * 16;
    int rBt = (lane & 7) + ((lane >> 3) & 1) * 8;
    int cBb = (lane >> 4) * 16;

    float acc[4][4] = {};
#pragma unroll
    for (int ks = 0; ks < 8; ks++) {
        u32 a0, a1, a2, a3;
        ldm4t(a0, a1, a2, a3, sb + VN + off128(ks * 16 + rAt, cAb));
#pragma unroll
        for (int jb = 0; jb < 2; jb++) {
            u32 b0, b1, b2, b3;
            ldm4t(b0, b1, b2, b3,
                  sb + KN + off128(ks * 16 + rBt, (n0 + jb * 16) * 2 + cBb));
            mma16816(acc[2 * jb],     a0, a1, a2, a3, b0, b1);
            mma16816(acc[2 * jb + 1], a0, a1, a2, a3, b2, b3);
        }
    }

    u32* kvout = g_kvh + (size_t)bid * (MM * DD / 2);
#pragma unroll
    for (int j = 0; j < 4; j++) {
        int dc = n0 + (j >> 1) * 16 + (j & 1) * 8 + tg * 2;
        kvout[(size_t)(m0 + grp) * 32 + (dc >> 1)]     = rnd2h(acc[j][0], acc[j][1]);
        kvout[(size_t)(m0 + grp + 8) * 32 + (dc >> 1)] = rnd2h(acc[j][2], acc[j][3]);
    }

    {
        float* ksp = (float*)(sm_ + KSP);
        int d = tid & 63, qd = tid >> 6;
        float s = 0.f;
#pragma unroll 8
        for (int cc = 0; cc < 32; cc++)
            s += __half2float(*(const __half*)(sm_ + KN + off128(qd * 32 + cc, d * 2)));
        ksp[qd * 64 + d] = s;
    }
    __syncthreads();
    if (tid < 64) {
        const float* ksp = (const float*)(sm_ + KSP);
        g_ksum[(size_t)bid * DD + tid] =
            ksp[tid] + ksp[64 + tid] + ksp[128 + tid] + ksp[192 + tid];
    }
}

// ---------------------------------------------------------------------------
// Kernel B: exclusive prefix over chunks. Latency-optimized: 4 threads per
// element chain, each preloads its 8 chunks (MLP 8), shfl-scan over subs.
// ---------------------------------------------------------------------------
__global__ void __launch_bounds__(256) prefix_kernel()
{
    int blk = blockIdx.x;
    int nh = blk >> 4, seg = blk & 15;
    int n = nh / HH, h = nh % HH;
    int tid = threadIdx.x;
    int sub = tid & 3;
    int elem = seg * 64 + (tid >> 2);                  // uint2 index 0..1023
    const size_t gstr = (size_t)HH * (MM * DD / 2);    // u32 per chunk step
    u32* basep = g_kvh + (((size_t)(n * GG) * HH) + h) * (MM * DD / 2) + elem * 2;

    uint2 vals[8];
#pragma unroll
    for (int t = 0; t < 8; t++)
        vals[t] = *(uint2*)(basep + (size_t)(sub * 8 + t) * gstr);

    float4 tot = make_float4(0.f, 0.f, 0.f, 0.f);
#pragma unroll
    for (int t = 0; t < 8; t++) {
        float2 f0 = h2f(vals[t].x), f1 = h2f(vals[t].y);
        tot.x += f0.x; tot.y += f0.y; tot.z += f1.x; tot.w += f1.y;
    }
    float4 incl = tot;
#pragma unroll
    for (int d = 1; d < 4; d <<= 1) {
        float4 t;
        t.x = __shfl_up_sync(0xffffffffu, incl.x, d, 4);
        t.y = __shfl_up_sync(0xffffffffu, incl.y, d, 4);
        t.z = __shfl_up_sync(0xffffffffu, incl.z, d, 4);
        t.w = __shfl_up_sync(0xffffffffu, incl.w, d, 4);
        if (sub >= d) { incl.x += t.x; incl.y += t.y; incl.z += t.z; incl.w += t.w; }
    }
    float4 run = make_float4(incl.x - tot.x, incl.y - tot.y,
                             incl.z - tot.z, incl.w - tot.w);
#pragma unroll
    for (int t = 0; t < 8; t++) {
        uint2 o = make_uint2(rnd2h(run.x, run.y), rnd2h(run.z, run.w));
        float2 f0 = h2f(vals[t].x), f1 = h2f(vals[t].y);
        *(uint2*)(basep + (size_t)(sub * 8 + t) * gstr) = o;
        run.x += f0.x; run.y += f0.y; run.z += f1.x; run.w += f1.y;
    }

    if (seg == 0 && tid < 64) {
        int fe = tid >> 2;
        const size_t kstr = (size_t)HH * DD;
        float* kb = g_ksum + (((size_t)(n * GG) * HH) + h) * DD + fe * 4;
        float4 kv[8];
#pragma unroll
        for (int t = 0; t < 8; t++)
            kv[t] = *(float4*)(kb + (size_t)(sub * 8 + t) * kstr);
        float4 kt = make_float4(0.f, 0.f, 0.f, 0.f);
#pragma unroll
        for (int t = 0; t < 8; t++) {
            kt.x += kv[t].x; kt.y += kv[t].y; kt.z += kv[t].z; kt.w += kv[t].w;
        }
        float4 ki = kt;
#pragma unroll
        for (int d = 1; d < 4; d <<= 1) {
            float4 t;
            t.x = __shfl_up_sync(0xffffffffu, ki.x, d, 4);
            t.y = __shfl_up_sync(0xffffffffu, ki.y, d, 4);
            t.z = __shfl_up_sync(0xffffffffu, ki.z, d, 4);
            t.w = __shfl_up_sync(0xffffffffu, ki.w, d, 4);
            if (sub >= d) { ki.x += t.x; ki.y += t.y; ki.z += t.z; ki.w += t.w; }
        }
        float4 kr = make_float4(ki.x - kt.x, ki.y - kt.y, ki.z - kt.z, ki.w - kt.w);
#pragma unroll
        for (int t = 0; t < 8; t++) {
            float4 cur = kv[t];
            *(float4*)(kb + (size_t)(sub * 8 + t) * kstr) = kr;
            kr.x += cur.x; kr.y += cur.y; kr.z += cur.z; kr.w += cur.w;
        }
    }
}

// ---------------------------------------------------------------------------
// Kernel C: EXACT R15 version (139.3us): pure fp16 MMA, z via N=72 MMA col,
// fp32 intra-z, cp.async KV', 3 CTAs/SM. planes: QH/KH/VN/WH. 57KB.
// ---------------------------------------------------------------------------
#define QHo 0
#define KHo 16384
#define VNo 32768
#define WHo 49152
#define SMEM_C 58368

__global__ void __launch_bounds__(256, 3) output_kernel(
    const float* __restrict__ q, const float* __restrict__ k,
    const float* __restrict__ v, float* __restrict__ out)
{
    extern __shared__ char sm_[];
    u32 sb = smem_u32(sm_);

    int tid = threadIdx.x, lane = tid & 31, wid = tid >> 5;
    int bid = blockIdx.x;
    int h = bid % HH;
    int gc = (bid / HH) % GG;
    int n = bid / (HH * GG);
    size_t base = (((size_t)n * LL + (size_t)gc * CC) * HH + h) * DD;

    // ---- KV' rows 0..63 via cp.async (512 x 16B) ----
    {
        const u32* kvp = g_kvh + (size_t)bid * (MM * DD / 2);
#pragma unroll
        for (int t = 0; t < 2; t++) {
            int i = tid + t * 256;
            int m = i >> 3, du = (i & 7) * 4;
            u32 dst = sb + WHo + off128(m, du * 4);
            const void* src = kvp + (size_t)m * 32 + du;
            asm volatile("cp.async.ca.shared.global [%0], [%1], 16;"
                         :: "r"(dst), "l"(src));
        }
        asm volatile("cp.async.commit_group;");
    }

    // ---- merged, batched q/k/v loader (all rounded to fp16) ----
#pragma unroll
    for (int bb = 0; bb < 4; bb++) {
        float4 qr[2], kr[2], vr[2];
#pragma unroll
        for (int t = 0; t < 2; t++) {
            int i = tid + (bb * 2 + t) * 256;
            int c = i >> 4, dq = (i & 15) << 2;
            size_t off = base + (size_t)c * (HH * DD) + dq;
            qr[t] = *(const float4*)(q + off);
            kr[t] = *(const float4*)(k + off);
            vr[t] = *(const float4*)(v + off);
        }
#pragma unroll
        for (int t = 0; t < 2; t++) {
            int i = tid + (bb * 2 + t) * 256;
            int c = i >> 4, dq = (i & 15) << 2;
            u32 ob = off128(c, dq * 2);
            *(uint2*)(sm_ + QHo + ob) =
                make_uint2(rnd2h(phi(qr[t].x), phi(qr[t].y)),
                           rnd2h(phi(qr[t].z), phi(qr[t].w)));
            *(uint2*)(sm_ + KHo + ob) =
                make_uint2(rnd2h(phi(kr[t].x), phi(kr[t].y)),
                           rnd2h(phi(kr[t].z), phi(kr[t].w)));
            *(uint2*)(sm_ + VNo + ob) =
                make_uint2(rnd2h(vr[t].x, vr[t].y), rnd2h(vr[t].z, vr[t].w));
        }
    }
    // ---- KV' row 64 = ksum_prev, rows 65..71 zero ----
    if (tid < 16) {
        float4 t4 = *(const float4*)(g_ksum + (size_t)bid * DD + tid * 4);
        *(uint2*)(sm_ + WHo + off128(64, tid * 8)) =
            make_uint2(rnd2h(t4.x, t4.y), rnd2h(t4.z, t4.w));
    }
    if (tid < 224) {
        int row = 65 + (tid >> 5), cu = tid & 31;
        *(u32*)(sm_ + WHo + row * 128 + cu * 4) = 0u;
    }
    asm volatile("cp.async.wait_group 0;" ::: "memory");
    __syncthreads();

    const int perm[8] = { 0, 1, 2, 3, 7, 6, 5, 4 };
    int wb = perm[wid];
    int m0 = wb * 16;
    int grp = lane >> 2, tg = lane & 3;
    int rA = m0 + ((lane >> 3) & 1) * 8 + (lane & 7);
    int rB = (lane >> 4) * 8 + (lane & 7);
    int kbA0 = 16 * (lane >> 4);
    int kbB0 = 16 * ((lane >> 3) & 1);
    int rBt = (lane & 7) + ((lane >> 3) & 1) * 8;
    int cBb = (lane >> 4) * 16;
    int r9 = 64 + (lane & 7);
    int r0 = m0 + grp, r1 = r0 + 8;

    // ---- cache Q fragments ----
    u32 qh[4][4];
#pragma unroll
    for (int ks = 0; ks < 4; ks++)
        ldm4(qh[ks][0], qh[ks][1], qh[ks][2], qh[ks][3], sb + QHo + off128(rA, 32 * ks + kbA0));

    float accO[9][4] = {};

    // ---- inter: O += Q KV'^T (N=72, z col 64) ----
#pragma unroll
    for (int ks = 0; ks < 4; ks++) {
        int kb = 32 * ks + kbB0;
#pragma unroll
        for (int jb = 0; jb < 4; jb++) {
            u32 b0, b1, b2, b3;
            ldm4(b0, b1, b2, b3, sb + WHo + off128(jb * 16 + rB, kb));
            mma16816(accO[2 * jb],     qh[ks][0], qh[ks][1], qh[ks][2], qh[ks][3], b0, b1);
            mma16816(accO[2 * jb + 1], qh[ks][0], qh[ks][1], qh[ks][2], qh[ks][3], b2, b3);
        }
        u32 b0, b1;
        ldm2(b0, b1, sb + WHo + off128(r9, kb));
        mma16816(accO[8], qh[ks][0], qh[ks][1], qh[ks][2], qh[ks][3], b0, b1);
    }

    // ---- S blocks (jb <= wb): GEMM1 -> mask (+fp32 z) -> round -> intra ----
    float zs0 = 0.f, zs1 = 0.f;
#pragma unroll
    for (int jb = 0; jb < 8; jb++) {
        if (jb <= wb) {
            float s0[4] = {}, s1[4] = {};
#pragma unroll
            for (int ks = 0; ks < 4; ks++) {
                u32 b0, b1, b2, b3;
                ldm4(b0, b1, b2, b3, sb + KHo + off128(jb * 16 + rB, 32 * ks + kbB0));
                mma16816(s0, qh[ks][0], qh[ks][1], qh[ks][2], qh[ks][3], b0, b1);
                mma16816(s1, qh[ks][0], qh[ks][1], qh[ks][2], qh[ks][3], b2, b3);
            }
            int cA = jb * 16 + tg * 2, cB = cA + 8;
            if (cA > r0)     s0[0] = 0.f;
            if (cA + 1 > r0) s0[1] = 0.f;
            if (cA > r1)     s0[2] = 0.f;
            if (cA + 1 > r1) s0[3] = 0.f;
            if (cB > r0)     s1[0] = 0.f;
            if (cB + 1 > r0) s1[1] = 0.f;
            if (cB > r1)     s1[2] = 0.f;
            if (cB + 1 > r1) s1[3] = 0.f;
            zs0 += (s0[0] + s0[1]) + (s1[0] + s1[1]);
            zs1 += (s0[2] + s0[3]) + (s1[2] + s1[3]);
            u32 sh0 = rnd2h(s0[0], s0[1]);
            u32 sh1 = rnd2h(s0[2], s0[3]);
            u32 sh2 = rnd2h(s1[0], s1[1]);
            u32 sh3 = rnd2h(s1[2], s1[3]);
#pragma unroll
            for (int vjb = 0; vjb < 4; vjb++) {
                u32 b0, b1, b2, b3;
                ldm4t(b0, b1, b2, b3,
                      sb + VNo + off128(jb * 16 + rBt, vjb * 32 + cBb));
                mma16816(accO[2 * vjb],     sh0, sh1, sh2, sh3, b0, b1);
                mma16816(accO[2 * vjb + 1], sh0, sh1, sh2, sh3, b2, b3);
            }
        }
    }
    zs0 += __shfl_xor_sync(0xffffffffu, zs0, 1);
    zs0 += __shfl_xor_sync(0xffffffffu, zs0, 2);
    zs1 += __shfl_xor_sync(0xffffffffu, zs1, 1);
    zs1 += __shfl_xor_sync(0xffffffffu, zs1, 2);

    // ---- normalize + store ----
    float zr0 = __shfl_sync(0xffffffffu, accO[8][0], lane & 28);
    float zr1 = __shfl_sync(0xffffffffu, accO[8][2], lane & 28);
    float rz0 = 1.0f / (zr0 + zs0 + EPSF);
    float rz1 = 1.0f / (zr1 + zs1 + EPSF);
    float* op0 = out + (((size_t)n * LL + (size_t)gc * CC + r0) * HH + h) * MM;
    float* op1 = op0 + (size_t)8 * HH * MM;
#pragma unroll
    for (int j = 0; j < 8; j++) {
        int c0 = j * 8 + tg * 2;
        *(float2*)(op0 + c0) = make_float2(accO[j][0] * rz0, accO[j][1] * rz0);
        *(float2*)(op1 + c0) = make_float2(accO[j][2] * rz1, accO[j][3] * rz1);
    }
}

// ---------------------------------------------------------------------------
extern "C" void kernel_launch(void* const* d_in, const int* in_sizes, int n_in,
                              void* d_out, int out_size)
{
    const float* q = (const float*)d_in[0];
    const float* k = (const float*)d_in[1];
    const float* v = (const float*)d_in[2];
    float* out = (float*)d_out;

    const int SMEM_A = 33792;

    cudaFuncSetAttribute(chunk_state_kernel,
                         cudaFuncAttributeMaxDynamicSharedMemorySize, SMEM_A);
    cudaFuncSetAttribute(output_kernel,
                         cudaFuncAttributeMaxDynamicSharedMemorySize, SMEM_C);

    chunk_state_kernel<<<NN * GG * HH, 256, SMEM_A>>>(k, v);
    prefix_kernel<<<NN * HH * 16, 256>>>();
    output_kernel<<<NN * GG * HH, 256, SMEM_C>>>(q, k, v, out);
}